// round 4
// baseline (speedup 1.0000x reference)
#include <cuda_runtime.h>
#include <math.h>

// Problem constants
#define Bsz    8
#define Tlen   1024
#define EMB    1024
#define NHEADS 16
#define HD     64
#define CHUNK  64

#define MTOT (Bsz * Tlen)          // 8192 rows

// ---------------------------------------------------------------------------
// Scratch (device globals — allocation-free per harness rules)
// ---------------------------------------------------------------------------
__device__ float g_q[MTOT * EMB];
__device__ float g_k[MTOT * EMB];
__device__ float g_v[MTOT * EMB];
__device__ float g_attn[MTOT * EMB];

// ---------------------------------------------------------------------------
// GEMM: C[M,N] = A[M,K] * B[N,K]^T + bias[N]      (torch Linear semantics)
// M=8192, N=K=1024. BM=BN=64, BK=16, 256 threads, 4x4 micro tile.
// ---------------------------------------------------------------------------
#define BM 64
#define BN 64
#define BK 16

__global__ __launch_bounds__(256)
void gemm_nt_bias(const float* __restrict__ A, const float* __restrict__ B,
                  const float* __restrict__ bias, float* __restrict__ C,
                  int M, int N, int K)
{
    __shared__ float As[BK][BM + 4];   // transposed: As[k][m]
    __shared__ float Bs[BK][BN + 4];   // transposed: Bs[k][n]

    const int tid = threadIdx.x;
    const int tx = tid & 15;           // 0..15  -> n micro
    const int ty = tid >> 4;           // 0..15  -> m micro
    const int mBase = blockIdx.y * BM;
    const int nBase = blockIdx.x * BN;

    const int lrow = tid >> 2;         // 0..63
    const int lk   = (tid & 3) * 4;    // 0,4,8,12

    const float* Ag = A + (size_t)(mBase + lrow) * K + lk;
    const float* Bg = B + (size_t)(nBase + lrow) * K + lk;

    float acc[4][4];
#pragma unroll
    for (int i = 0; i < 4; i++)
#pragma unroll
        for (int j = 0; j < 4; j++) acc[i][j] = 0.f;

    for (int k0 = 0; k0 < K; k0 += BK) {
        float4 a = *(const float4*)(Ag + k0);
        float4 b = *(const float4*)(Bg + k0);
        As[lk + 0][lrow] = a.x; As[lk + 1][lrow] = a.y;
        As[lk + 2][lrow] = a.z; As[lk + 3][lrow] = a.w;
        Bs[lk + 0][lrow] = b.x; Bs[lk + 1][lrow] = b.y;
        Bs[lk + 2][lrow] = b.z; Bs[lk + 3][lrow] = b.w;
        __syncthreads();

#pragma unroll
        for (int kk = 0; kk < BK; kk++) {
            float4 av = *(const float4*)(&As[kk][ty * 4]);
            float4 bv = *(const float4*)(&Bs[kk][tx * 4]);
            float am[4] = {av.x, av.y, av.z, av.w};
            float bn[4] = {bv.x, bv.y, bv.z, bv.w};
#pragma unroll
            for (int i = 0; i < 4; i++)
#pragma unroll
                for (int j = 0; j < 4; j++)
                    acc[i][j] = fmaf(am[i], bn[j], acc[i][j]);
        }
        __syncthreads();
    }

    const int col = nBase + tx * 4;
    float4 bv = *(const float4*)(bias + col);
#pragma unroll
    for (int i = 0; i < 4; i++) {
        int row = mBase + ty * 4 + i;
        float4 o;
        o.x = acc[i][0] + bv.x;
        o.y = acc[i][1] + bv.y;
        o.z = acc[i][2] + bv.z;
        o.w = acc[i][3] + bv.w;
        *(float4*)(C + (size_t)row * N + col) = o;
    }
}

// ---------------------------------------------------------------------------
// Fused attention, flash-style.
// Mask: key j masked for query i iff j>i AND same CHUNK(=64) block
//       => only the diagonal 64x64 key tile is (triangularly) masked.
// Block: (q-tile, head, batch). 256 threads = 64 query rows x 4 subs.
// Each sub owns 16 keys during score compute and 16 output dims during PV.
// ---------------------------------------------------------------------------
#define QT 64
#define KT 64
#define LDP 68   // padded row length (floats), float4-aligned, bank-friendly

__global__ __launch_bounds__(256)
void attn_kernel(const float* __restrict__ Q, const float* __restrict__ K,
                 const float* __restrict__ V, const float* __restrict__ scale_p,
                 float* __restrict__ O)
{
    extern __shared__ float smem[];
    float (*Qs)[LDP] = (float(*)[LDP])(smem);
    float (*Ks)[LDP] = (float(*)[LDP])(smem + QT * LDP);
    float (*Vs)[LDP] = (float(*)[LDP])(smem + 2 * QT * LDP);
    float (*Ps)[LDP] = (float(*)[LDP])(smem + 3 * QT * LDP);

    const int tid = threadIdx.x;
    const int qi  = tid >> 2;      // 0..63 query row in tile
    const int sub = tid & 3;       // 0..3
    const int qt = blockIdx.x, h = blockIdx.y, b = blockIdx.z;
    const float scale = scale_p[0];

    // Load Q tile (each thread: 16 floats = quarter of one row)
    {
        const int r = tid >> 2, c = (tid & 3) * 16;
        const float* Qb = Q + ((size_t)b * Tlen + qt * QT + r) * EMB + h * HD + c;
#pragma unroll
        for (int j = 0; j < 4; j++)
            *(float4*)&Qs[r][c + 4 * j] = *(const float4*)(Qb + 4 * j);
    }

    float m = -INFINITY, l = 0.f;
    float acc[16];
#pragma unroll
    for (int i = 0; i < 16; i++) acc[i] = 0.f;

    const int kbase = sub * 16;

    for (int kt = 0; kt < Tlen / KT; kt++) {
        __syncthreads();   // protects Ks/Vs/Ps reuse across iterations (and Qs first iter)
        {
            const int r = tid >> 2, c = (tid & 3) * 16;
            const float* Kb = K + ((size_t)b * Tlen + kt * KT + r) * EMB + h * HD + c;
            const float* Vb = V + ((size_t)b * Tlen + kt * KT + r) * EMB + h * HD + c;
#pragma unroll
            for (int j = 0; j < 4; j++) {
                *(float4*)&Ks[r][c + 4 * j] = *(const float4*)(Kb + 4 * j);
                *(float4*)&Vs[r][c + 4 * j] = *(const float4*)(Vb + 4 * j);
            }
        }
        __syncthreads();

        // Scores: this thread's 16 keys vs its query row
        float s[16];
#pragma unroll
        for (int j = 0; j < 16; j++) {
            float a0 = 0.f, a1 = 0.f, a2 = 0.f, a3 = 0.f;
#pragma unroll
            for (int d = 0; d < HD; d += 4) {
                float4 qv = *(const float4*)&Qs[qi][d];
                float4 kv = *(const float4*)&Ks[kbase + j][d];
                a0 = fmaf(qv.x, kv.x, a0);
                a1 = fmaf(qv.y, kv.y, a1);
                a2 = fmaf(qv.z, kv.z, a2);
                a3 = fmaf(qv.w, kv.w, a3);
            }
            s[j] = ((a0 + a1) + (a2 + a3)) * scale;
        }
        if (kt == qt) {
#pragma unroll
            for (int j = 0; j < 16; j++)
                if (kbase + j > qi) s[j] = -INFINITY;
        }

        // Online softmax (combine across the 4 subs of this query row)
        float tmax = s[0];
#pragma unroll
        for (int j = 1; j < 16; j++) tmax = fmaxf(tmax, s[j]);
        tmax = fmaxf(tmax, __shfl_xor_sync(0xffffffffu, tmax, 1));
        tmax = fmaxf(tmax, __shfl_xor_sync(0xffffffffu, tmax, 2));
        float mnew = fmaxf(m, tmax);
        float corr = __expf(m - mnew);   // 0 when m == -inf

        float tsum = 0.f;
#pragma unroll
        for (int j = 0; j < 16; j++) {
            float p = __expf(s[j] - mnew);
            Ps[qi][kbase + j] = p;
            tsum += p;
        }
        tsum += __shfl_xor_sync(0xffffffffu, tsum, 1);
        tsum += __shfl_xor_sync(0xffffffffu, tsum, 2);
        l = l * corr + tsum;
        m = mnew;
#pragma unroll
        for (int i = 0; i < 16; i++) acc[i] *= corr;

        __syncthreads();   // Ps visible to all subs of this row

        // PV: this thread accumulates 16 output dims over all 64 keys
#pragma unroll 4
        for (int kn = 0; kn < KT; kn++) {
            float p = Ps[qi][kn];
#pragma unroll
            for (int i = 0; i < 16; i += 4) {
                float4 vv = *(const float4*)&Vs[kn][sub * 16 + i];
                acc[i + 0] = fmaf(p, vv.x, acc[i + 0]);
                acc[i + 1] = fmaf(p, vv.y, acc[i + 1]);
                acc[i + 2] = fmaf(p, vv.z, acc[i + 2]);
                acc[i + 3] = fmaf(p, vv.w, acc[i + 3]);
            }
        }
    }

    const float linv = 1.f / l;
    float* Ob = O + ((size_t)b * Tlen + qt * QT + qi) * EMB + h * HD + sub * 16;
#pragma unroll
    for (int i = 0; i < 16; i += 4) {
        float4 o = make_float4(acc[i] * linv, acc[i + 1] * linv,
                               acc[i + 2] * linv, acc[i + 3] * linv);
        *(float4*)(Ob + i) = o;
    }
}

// ---------------------------------------------------------------------------
// Launch
// ---------------------------------------------------------------------------
extern "C" void kernel_launch(void* const* d_in, const int* in_sizes, int n_in,
                              void* d_out, int out_size)
{
    const float* x     = (const float*)d_in[0];
    const float* Wq    = (const float*)d_in[1];
    const float* bq    = (const float*)d_in[2];
    const float* Wk    = (const float*)d_in[3];
    const float* bk    = (const float*)d_in[4];
    const float* Wv    = (const float*)d_in[5];
    const float* bv    = (const float*)d_in[6];
    const float* Wo    = (const float*)d_in[7];
    const float* bo    = (const float*)d_in[8];
    const float* ascl  = (const float*)d_in[9];
    float* out = (float*)d_out;

    float *q, *k, *v, *attn;
    cudaGetSymbolAddress((void**)&q,    g_q);
    cudaGetSymbolAddress((void**)&k,    g_k);
    cudaGetSymbolAddress((void**)&v,    g_v);
    cudaGetSymbolAddress((void**)&attn, g_attn);

    const int M = MTOT, N = EMB, K = EMB;
    dim3 ggrid(N / BN, M / BM);   // (16, 128)
    dim3 gblk(256);

    gemm_nt_bias<<<ggrid, gblk>>>(x, Wq, bq, q, M, N, K);
    gemm_nt_bias<<<ggrid, gblk>>>(x, Wk, bk, k, M, N, K);
    gemm_nt_bias<<<ggrid, gblk>>>(x, Wv, bv, v, M, N, K);

    const int smem_bytes = 4 * QT * LDP * (int)sizeof(float);   // 69,632 B
    static int attr_set = 0;
    cudaFuncSetAttribute(attn_kernel,
                         cudaFuncAttributeMaxDynamicSharedMemorySize, smem_bytes);
    (void)attr_set;

    dim3 agrid(Tlen / QT, NHEADS, Bsz);  // (16, 16, 8)
    attn_kernel<<<agrid, 256, smem_bytes>>>(q, k, v, ascl, attn);

    gemm_nt_bias<<<ggrid, gblk>>>(attn, Wo, bo, out, M, N, K);
}